// round 1
// baseline (speedup 1.0000x reference)
#include <cuda_runtime.h>
#include <math.h>

// Problem dims (fixed by the dataset)
#define N_B   256
#define I_DIM 32
#define J_DIM 32
#define K_DIM 256

// Phase-1 tiling
#define KC  32            // K chunk
#define PAD 40            // smem row stride in floats (bank-conflict-free for LDS.64 frag loads)
#define XR  128           // x rows per CTA (4 a's)
#define ZR  256           // z rows per CTA (8 b's)
#define SMEM_FLOATS (2*XR*PAD + 2*ZR*PAD)
#define SMEM_BYTES  (SMEM_FLOATS * 4)

// Scratch (device globals: allocation-free rule)
__device__ __align__(256) float g_xr[N_B * I_DIM * K_DIM];
__device__ __align__(256) float g_zr[N_B * J_DIM * K_DIM];
__device__ __align__(256) float g_S[N_B * N_B];

// ---------------------------------------------------------------------------
// helpers
// ---------------------------------------------------------------------------
__device__ __forceinline__ unsigned rna_tf32(float v) {
    unsigned r;
    asm("cvt.rna.tf32.f32 %0, %1;" : "=r"(r) : "f"(v));
    return r;
}

__device__ __forceinline__ void cp16(unsigned dst, const float* src) {
    asm volatile("cp.async.cg.shared.global [%0], [%1], 16;\n" :: "r"(dst), "l"(src));
}

__device__ __forceinline__ void mma_tf32(float c[4], const unsigned a[4], const unsigned b[2]) {
    asm volatile(
        "mma.sync.aligned.m16n8k8.row.col.f32.tf32.tf32.f32 "
        "{%0,%1,%2,%3}, {%4,%5,%6,%7}, {%8,%9}, {%0,%1,%2,%3};\n"
        : "+f"(c[0]), "+f"(c[1]), "+f"(c[2]), "+f"(c[3])
        : "r"(a[0]), "r"(a[1]), "r"(a[2]), "r"(a[3]), "r"(b[0]), "r"(b[1]));
}

// ---------------------------------------------------------------------------
// Phase 0: round inputs to tf32 (rna) once; removes cvt from hot loop & bias
// ---------------------------------------------------------------------------
__global__ void round_kernel(const float* __restrict__ x, const float* __restrict__ z) {
    const int n4 = (N_B * I_DIM * K_DIM) / 4;  // 524288 float4 per tensor
    int idx = blockIdx.x * blockDim.x + threadIdx.x;
    int stride = gridDim.x * blockDim.x;
    for (int i = idx; i < 2 * n4; i += stride) {
        const float4* s;
        float4* d;
        if (i < n4) { s = ((const float4*)x) + i;        d = ((float4*)g_xr) + i; }
        else        { s = ((const float4*)z) + (i - n4); d = ((float4*)g_zr) + (i - n4); }
        float4 v = *s;
        float4 o;
        o.x = __uint_as_float(rna_tf32(v.x));
        o.y = __uint_as_float(rna_tf32(v.y));
        o.z = __uint_as_float(rna_tf32(v.z));
        o.w = __uint_as_float(rna_tf32(v.w));
        *d = o;
    }
}

// ---------------------------------------------------------------------------
// Phase 1: fused sim-GEMM + softmax-over-i reduction -> S[a][b]
// CTA: 128 x-rows (4 a's) x 256 z-rows (8 b's); 8 warps, warp tile 64x64.
// ---------------------------------------------------------------------------
__device__ __forceinline__ void issue_chunk(const float* __restrict__ xg,
                                            const float* __restrict__ zg,
                                            float* xs, float* zs,
                                            int stage, int chunk, int tid) {
    const int kc = chunk * KC;
    float* xd = xs + stage * XR * PAD;
    float* zd = zs + stage * ZR * PAD;
#pragma unroll
    for (int q = 0; q < 4; ++q) {            // 1024 float4 for x tile
        int it = tid + 256 * q;
        int row = it >> 3, seg = it & 7;
        cp16((unsigned)__cvta_generic_to_shared(xd + row * PAD + seg * 4),
             xg + row * K_DIM + kc + seg * 4);
    }
#pragma unroll
    for (int q = 0; q < 8; ++q) {            // 2048 float4 for z tile
        int it = tid + 256 * q;
        int row = it >> 3, seg = it & 7;
        cp16((unsigned)__cvta_generic_to_shared(zd + row * PAD + seg * 4),
             zg + row * K_DIM + kc + seg * 4);
    }
    asm volatile("cp.async.commit_group;\n" ::);
}

__device__ __forceinline__ void compute_chunk(const float* xs, const float* zs,
                                              int stage, int w_m, int w_n,
                                              int g, int tg, float acc[4][8][4]) {
    const float* xss = xs + stage * XR * PAD;
    const float* zss = zs + stage * ZR * PAD;
    const int arow = w_m * 64 + g;
    const int bcol = w_n * 64 + g;
#pragma unroll
    for (int ks = 0; ks < 4; ++ks) {
        // k permutation: mma col c <-> chunk k offset ks*8 + 2*(c&3) + (c>>2)
        // -> fragment slots (tg, tg+4) are ADJACENT in smem => LDS.64
        const int ko = ks * 8 + 2 * tg;
        unsigned a[4][4];
#pragma unroll
        for (int mf = 0; mf < 4; ++mf) {
            float2 p0 = *(const float2*)(xss + (arow + mf * 16) * PAD + ko);
            float2 p1 = *(const float2*)(xss + (arow + mf * 16 + 8) * PAD + ko);
            a[mf][0] = __float_as_uint(p0.x);   // (row g,    col tg)
            a[mf][1] = __float_as_uint(p1.x);   // (row g+8,  col tg)
            a[mf][2] = __float_as_uint(p0.y);   // (row g,    col tg+4)
            a[mf][3] = __float_as_uint(p1.y);   // (row g+8,  col tg+4)
        }
        unsigned b[8][2];
#pragma unroll
        for (int nf = 0; nf < 8; ++nf) {
            float2 p = *(const float2*)(zss + (bcol + nf * 8) * PAD + ko);
            b[nf][0] = __float_as_uint(p.x);    // (k tg,   col g)
            b[nf][1] = __float_as_uint(p.y);    // (k tg+4, col g)
        }
#pragma unroll
        for (int mf = 0; mf < 4; ++mf)
#pragma unroll
            for (int nf = 0; nf < 8; ++nf)
                mma_tf32(acc[mf][nf], a[mf], b[nf]);
    }
}

__global__ void __launch_bounds__(256, 1) sim_kernel() {
    extern __shared__ float sm[];
    float* xs = sm;
    float* zs = sm + 2 * XR * PAD;

    const int tid  = threadIdx.x;
    const int lane = tid & 31;
    const int wid  = tid >> 5;
    const int g    = lane >> 2;
    const int tg   = lane & 3;
    const int w_m  = wid & 1;    // 2 warps in m
    const int w_n  = wid >> 1;   // 4 warps in n

    const float* xg = g_xr + (size_t)blockIdx.y * 128 * K_DIM;
    const float* zg = g_zr + (size_t)blockIdx.x * 256 * K_DIM;

    float acc[4][8][4];
#pragma unroll
    for (int mf = 0; mf < 4; ++mf)
#pragma unroll
        for (int nf = 0; nf < 8; ++nf)
#pragma unroll
            for (int q = 0; q < 4; ++q) acc[mf][nf][q] = 0.0f;

    issue_chunk(xg, zg, xs, zs, 0, 0, tid);

#pragma unroll 1
    for (int c = 0; c < 8; ++c) {
        if (c + 1 < 8) {
            issue_chunk(xg, zg, xs, zs, (c + 1) & 1, c + 1, tid);
            asm volatile("cp.async.wait_group 1;\n" ::);
        } else {
            asm volatile("cp.async.wait_group 0;\n" ::);
        }
        __syncthreads();
        compute_chunk(xs, zs, c & 1, w_m, w_n, g, tg, acc);
        __syncthreads();
    }

    // ---- fused epilogue: softmax over i (32 rows per a) then sum over j ----
    // Warp covers 2 a's (ag=0,1 -> m-frag pairs {0,1},{2,3}) and 2 b's (bg=nf>>2).
    float colsum[2][2] = {{0.f, 0.f}, {0.f, 0.f}};
#pragma unroll
    for (int ag = 0; ag < 2; ++ag) {
#pragma unroll
        for (int nf = 0; nf < 8; ++nf) {
#pragma unroll
            for (int par = 0; par < 2; ++par) {
                // column = nf*8 + 2*tg + par; this thread holds rows g,g+8,g+16,g+24
                float v0 = acc[ag * 2][nf][par];
                float v1 = acc[ag * 2][nf][par + 2];
                float v2 = acc[ag * 2 + 1][nf][par];
                float v3 = acc[ag * 2 + 1][nf][par + 2];
                float mx = fmaxf(fmaxf(v0, v1), fmaxf(v2, v3));
                mx = fmaxf(mx, __shfl_xor_sync(0xffffffffu, mx, 4));
                mx = fmaxf(mx, __shfl_xor_sync(0xffffffffu, mx, 8));
                mx = fmaxf(mx, __shfl_xor_sync(0xffffffffu, mx, 16));
                float e0 = __expf(v0 - mx), e1 = __expf(v1 - mx);
                float e2 = __expf(v2 - mx), e3 = __expf(v3 - mx);
                float den = e0 + e1 + e2 + e3;
                float num = e0 * v0 + e1 * v1 + e2 * v2 + e3 * v3;
                den += __shfl_xor_sync(0xffffffffu, den, 4);
                num += __shfl_xor_sync(0xffffffffu, num, 4);
                den += __shfl_xor_sync(0xffffffffu, den, 8);
                num += __shfl_xor_sync(0xffffffffu, num, 8);
                den += __shfl_xor_sync(0xffffffffu, den, 16);
                num += __shfl_xor_sync(0xffffffffu, num, 16);
                colsum[ag][nf >> 2] += num / den;   // sum_i softmax_i(sim)*sim for this j
            }
        }
    }
    // sum over the 4 tg groups (each holds a disjoint set of 8 columns per b)
#pragma unroll
    for (int ag = 0; ag < 2; ++ag)
#pragma unroll
        for (int bg = 0; bg < 2; ++bg) {
            float cv = colsum[ag][bg];
            cv += __shfl_xor_sync(0xffffffffu, cv, 1);
            cv += __shfl_xor_sync(0xffffffffu, cv, 2);
            colsum[ag][bg] = cv;
        }
    if (lane == 0) {
#pragma unroll
        for (int ag = 0; ag < 2; ++ag)
#pragma unroll
            for (int bg = 0; bg < 2; ++bg) {
                int aIdx = blockIdx.y * 4 + w_m * 2 + ag;
                int bIdx = blockIdx.x * 8 + w_n * 2 + bg;
                g_S[aIdx * N_B + bIdx] = colsum[ag][bg] * (1.0f / (float)J_DIM);
            }
    }
}

// ---------------------------------------------------------------------------
// Phase 2: loss from S (256x256): mean_n [ lse_col(n) + lse_row(n) - 2*S[n][n] ]
// ---------------------------------------------------------------------------
__global__ void loss_kernel(float* __restrict__ out) {
    __shared__ float red[256];
    const int n = threadIdx.x;
    const float* S = g_S;
    float d = S[n * N_B + n];

    float m = -1e30f;
#pragma unroll 8
    for (int b = 0; b < N_B; ++b) m = fmaxf(m, S[n * N_B + b]);
    float s = 0.f;
#pragma unroll 8
    for (int b = 0; b < N_B; ++b) s += expf(S[n * N_B + b] - m);
    float lrow = m + logf(s);

    float m2 = -1e30f;
#pragma unroll 8
    for (int a = 0; a < N_B; ++a) m2 = fmaxf(m2, S[a * N_B + n]);
    float s2 = 0.f;
#pragma unroll 8
    for (int a = 0; a < N_B; ++a) s2 += expf(S[a * N_B + n] - m2);
    float lcol = m2 + logf(s2);

    red[n] = (lrow - d) + (lcol - d);
    __syncthreads();
#pragma unroll
    for (int off = 128; off > 0; off >>= 1) {
        if (n < off) red[n] += red[n + off];
        __syncthreads();
    }
    if (n == 0) out[0] = red[0] * (1.0f / (float)N_B);
}

// ---------------------------------------------------------------------------
extern "C" void kernel_launch(void* const* d_in, const int* in_sizes, int n_in,
                              void* d_out, int out_size) {
    (void)in_sizes; (void)n_in; (void)out_size;
    const float* x = (const float*)d_in[0];
    const float* z = (const float*)d_in[1];
    float* out = (float*)d_out;

    cudaFuncSetAttribute(sim_kernel, cudaFuncAttributeMaxDynamicSharedMemorySize, SMEM_BYTES);

    round_kernel<<<1024, 256>>>(x, z);
    sim_kernel<<<dim3(32, 64), 256, SMEM_BYTES>>>();
    loss_kernel<<<1, 256>>>(out);
}

// round 3
// speedup vs baseline: 1.6880x; 1.6880x over previous
#include <cuda_runtime.h>
#include <cuda_bf16.h>
#include <cstdint>
#include <math.h>

#define N_B   256
#define K_DIM 256
#define XR 128            // x rows per CTA (4 a's)
#define ZR 256            // z rows per CTA (8 b's)
#define KC 64             // bf16 per K chunk = 128 B per row
#define NCHUNK (K_DIM / KC)

// smem: per stage X tile 128*128B=16KB, Z tile 256*128B=32KB; 2 stages = 96KB
#define STAGE_BYTES 49152
#define SM_ALLOC (2 * STAGE_BYTES + 1024)

// device scratch (allocation-free rule)
__device__ __align__(1024) __nv_bfloat16 g_xh[(size_t)N_B * 32 * K_DIM];
__device__ __align__(1024) __nv_bfloat16 g_zh[(size_t)N_B * 32 * K_DIM];
__device__ __align__(256)  float g_S[N_B * N_B];
__device__ float g_part[2 * N_B];

// ---------------------------------------------------------------------------
// helpers
// ---------------------------------------------------------------------------
__device__ __forceinline__ uint32_t smem_u32(const void* p) {
    uint32_t a;
    asm("{ .reg .u64 t; cvta.to.shared.u64 t, %1; cvt.u32.u64 %0, t; }" : "=r"(a) : "l"(p));
    return a;
}
__device__ __forceinline__ void cp16(uint32_t dst, const void* src) {
    asm volatile("cp.async.cg.shared.global [%0], [%1], 16;\n" :: "r"(dst), "l"(src));
}
__device__ __forceinline__ void ldm_x4(uint32_t r[4], uint32_t addr) {
    asm volatile("ldmatrix.sync.aligned.m8n8.x4.shared.b16 {%0,%1,%2,%3}, [%4];"
                 : "=r"(r[0]), "=r"(r[1]), "=r"(r[2]), "=r"(r[3]) : "r"(addr));
}
__device__ __forceinline__ void mma_bf16(float c[4], const uint32_t a[4], const uint32_t b0,
                                         const uint32_t b1) {
    asm volatile(
        "mma.sync.aligned.m16n8k16.row.col.f32.bf16.bf16.f32 "
        "{%0,%1,%2,%3}, {%4,%5,%6,%7}, {%8,%9}, {%0,%1,%2,%3};\n"
        : "+f"(c[0]), "+f"(c[1]), "+f"(c[2]), "+f"(c[3])
        : "r"(a[0]), "r"(a[1]), "r"(a[2]), "r"(a[3]), "r"(b0), "r"(b1));
}
// SW128-style swizzle on byte offset within a 128B-row tile
__device__ __forceinline__ uint32_t swz(uint32_t off) {
    return off ^ ((off >> 3) & 0x70);
}

// ---------------------------------------------------------------------------
// Phase 0: fp32 -> bf16 (rn)
// ---------------------------------------------------------------------------
__global__ void round_kernel(const float* __restrict__ x, const float* __restrict__ z) {
    const int n4 = (N_B * 32 * K_DIM) / 4;
    int idx = blockIdx.x * blockDim.x + threadIdx.x;
    int stride = gridDim.x * blockDim.x;
    for (int i = idx; i < 2 * n4; i += stride) {
        const float4* s;
        __nv_bfloat16* d;
        int j;
        if (i < n4) { j = i;      s = ((const float4*)x) + j; d = g_xh + 4 * (size_t)j; }
        else        { j = i - n4; s = ((const float4*)z) + j; d = g_zh + 4 * (size_t)j; }
        float4 v = *s;
        __nv_bfloat162 p0 = __floats2bfloat162_rn(v.x, v.y);
        __nv_bfloat162 p1 = __floats2bfloat162_rn(v.z, v.w);
        uint2 o;
        o.x = *(uint32_t*)&p0;
        o.y = *(uint32_t*)&p1;
        *(uint2*)d = o;
    }
}

// ---------------------------------------------------------------------------
// Phase 1: bf16 mma.sync GEMM + fused softmax-over-i epilogue
// CTA: 128 x-rows (M) x 256 z-rows (N'); 8 warps, warp tile 64(m) x 64(n)
// ---------------------------------------------------------------------------
__device__ __forceinline__ void load_chunk(uint32_t xs, uint32_t zs,
                                           const __nv_bfloat16* __restrict__ xg,
                                           const __nv_bfloat16* __restrict__ zg,
                                           int c, int tid) {
    const int kc = c * KC;
#pragma unroll
    for (int q = 0; q < 4; ++q) {            // X tile: 128 rows x 8 segs
        int it = tid + 256 * q;
        int row = it >> 3, s = it & 7;
        cp16(xs + swz(row * 128 + s * 16), xg + (size_t)row * K_DIM + kc + s * 8);
    }
#pragma unroll
    for (int q = 0; q < 8; ++q) {            // Z tile: 256 rows x 8 segs
        int it = tid + 256 * q;
        int row = it >> 3, s = it & 7;
        cp16(zs + swz(row * 128 + s * 16), zg + (size_t)row * K_DIM + kc + s * 8);
    }
    asm volatile("cp.async.commit_group;\n" ::);
}

__device__ __forceinline__ void compute_chunk(uint32_t xs, uint32_t zs,
                                              int m0, int n0, int lane,
                                              float acc[4][8][4]) {
    // ldmatrix lane address components
    const int a_row16 = lane & 15;       // row within 16-row A tile
    const int a_half  = lane >> 4;       // 0: k0-7, 1: k8-15 (16B)
    const int b_grp   = lane >> 3;       // 0..3
    const int b_row   = lane & 7;
#pragma unroll
    for (int ks = 0; ks < 4; ++ks) {
        const uint32_t kcol = ks * 32;   // byte offset of k16 step within 128B row
        uint32_t a[4][4];
#pragma unroll
        for (int mf = 0; mf < 4; ++mf) {
            int row = m0 + mf * 16 + a_row16;
            ldm_x4(a[mf], xs + swz((uint32_t)row * 128 + kcol + a_half * 16));
        }
        uint32_t b[4][4];
#pragma unroll
        for (int pf = 0; pf < 4; ++pf) { // each pf covers two n8 tiles
            int row = n0 + pf * 16 + (b_grp >> 1) * 8 + b_row;
            ldm_x4(b[pf], zs + swz((uint32_t)row * 128 + kcol + (b_grp & 1) * 16));
        }
#pragma unroll
        for (int mf = 0; mf < 4; ++mf)
#pragma unroll
            for (int nf = 0; nf < 8; ++nf)
                mma_bf16(acc[mf][nf], a[mf], b[nf >> 1][(nf & 1) * 2],
                         b[nf >> 1][(nf & 1) * 2 + 1]);
    }
}

__global__ void __launch_bounds__(256, 1) sim_kernel() {
    extern __shared__ char sm_raw[];
    uint32_t base = (smem_u32(sm_raw) + 1023u) & ~1023u;

    const int tid  = threadIdx.x;
    const int lane = tid & 31;
    const int wid  = tid >> 5;
    const int w_m  = wid & 1;
    const int w_n  = wid >> 1;
    const int m0   = w_m * 64;
    const int n0   = w_n * 64;

    const __nv_bfloat16* xg = g_xh + (size_t)blockIdx.y * XR * K_DIM;
    const __nv_bfloat16* zg = g_zh + (size_t)blockIdx.x * ZR * K_DIM;

    const uint32_t xb[2] = { base, base + STAGE_BYTES };
    const uint32_t zb[2] = { base + 16384, base + STAGE_BYTES + 16384 };

    float acc[4][8][4];
#pragma unroll
    for (int mf = 0; mf < 4; ++mf)
#pragma unroll
        for (int nf = 0; nf < 8; ++nf)
#pragma unroll
            for (int q = 0; q < 4; ++q) acc[mf][nf][q] = 0.0f;

    load_chunk(xb[0], zb[0], xg, zg, 0, tid);

#pragma unroll 1
    for (int c = 0; c < NCHUNK; ++c) {
        if (c + 1 < NCHUNK) {
            load_chunk(xb[(c + 1) & 1], zb[(c + 1) & 1], xg, zg, c + 1, tid);
            asm volatile("cp.async.wait_group 1;\n" ::);
        } else {
            asm volatile("cp.async.wait_group 0;\n" ::);
        }
        __syncthreads();
        compute_chunk(xb[c & 1], zb[c & 1], m0, n0, lane, acc);
        __syncthreads();
    }

    // ---- fused epilogue: softmax over i, sum over j (identical to R1) ----
    const int tg = lane & 3;
    (void)tg;
    float colsum[2][2] = {{0.f, 0.f}, {0.f, 0.f}};
#pragma unroll
    for (int ag = 0; ag < 2; ++ag) {
#pragma unroll
        for (int nf = 0; nf < 8; ++nf) {
#pragma unroll
            for (int par = 0; par < 2; ++par) {
                float v0 = acc[ag * 2][nf][par];
                float v1 = acc[ag * 2][nf][par + 2];
                float v2 = acc[ag * 2 + 1][nf][par];
                float v3 = acc[ag * 2 + 1][nf][par + 2];
                float mx = fmaxf(fmaxf(v0, v1), fmaxf(v2, v3));
                mx = fmaxf(mx, __shfl_xor_sync(0xffffffffu, mx, 4));
                mx = fmaxf(mx, __shfl_xor_sync(0xffffffffu, mx, 8));
                mx = fmaxf(mx, __shfl_xor_sync(0xffffffffu, mx, 16));
                float e0 = __expf(v0 - mx), e1 = __expf(v1 - mx);
                float e2 = __expf(v2 - mx), e3 = __expf(v3 - mx);
                float den = e0 + e1 + e2 + e3;
                float num = e0 * v0 + e1 * v1 + e2 * v2 + e3 * v3;
                den += __shfl_xor_sync(0xffffffffu, den, 4);
                num += __shfl_xor_sync(0xffffffffu, num, 4);
                den += __shfl_xor_sync(0xffffffffu, den, 8);
                num += __shfl_xor_sync(0xffffffffu, num, 8);
                den += __shfl_xor_sync(0xffffffffu, den, 16);
                num += __shfl_xor_sync(0xffffffffu, num, 16);
                colsum[ag][nf >> 2] += num / den;
            }
        }
    }
#pragma unroll
    for (int ag = 0; ag < 2; ++ag)
#pragma unroll
        for (int bg = 0; bg < 2; ++bg) {
            float cv = colsum[ag][bg];
            cv += __shfl_xor_sync(0xffffffffu, cv, 1);
            cv += __shfl_xor_sync(0xffffffffu, cv, 2);
            colsum[ag][bg] = cv;
        }
    if (lane == 0) {
#pragma unroll
        for (int ag = 0; ag < 2; ++ag)
#pragma unroll
            for (int bg = 0; bg < 2; ++bg) {
                int aIdx = blockIdx.y * 4 + w_m * 2 + ag;
                int bIdx = blockIdx.x * 8 + w_n * 2 + bg;
                g_S[aIdx * N_B + bIdx] = colsum[ag][bg] * (1.0f / 32.0f);
            }
    }
}

// ---------------------------------------------------------------------------
// Phase 2a: per-n row/col logsumexp minus diag (512 warps)
// ---------------------------------------------------------------------------
__global__ void lse_kernel() {
    const int wg   = blockIdx.x * (blockDim.x >> 5) + (threadIdx.x >> 5);
    const int lane = threadIdx.x & 31;
    const int n    = wg & (N_B - 1);
    const bool col = wg >= N_B;

    float v[8];
#pragma unroll
    for (int k = 0; k < 8; ++k) {
        int idx = lane + 32 * k;
        v[k] = col ? g_S[idx * N_B + n] : g_S[n * N_B + idx];
    }
    float m = v[0];
#pragma unroll
    for (int k = 1; k < 8; ++k) m = fmaxf(m, v[k]);
#pragma unroll
    for (int o = 16; o > 0; o >>= 1) m = fmaxf(m, __shfl_xor_sync(0xffffffffu, m, o));
    float s = 0.f;
#pragma unroll
    for (int k = 0; k < 8; ++k) s += __expf(v[k] - m);
#pragma unroll
    for (int o = 16; o > 0; o >>= 1) s += __shfl_xor_sync(0xffffffffu, s, o);
    if (lane == 0) g_part[wg] = m + logf(s) - g_S[n * N_B + n];
}

// ---------------------------------------------------------------------------
// Phase 2b: final mean
// ---------------------------------------------------------------------------
__global__ void finish_kernel(float* __restrict__ out) {
    __shared__ float red[512];
    int t = threadIdx.x;
    red[t] = g_part[t];
    __syncthreads();
#pragma unroll
    for (int o = 256; o > 0; o >>= 1) {
        if (t < o) red[t] += red[t + o];
        __syncthreads();
    }
    if (t == 0) out[0] = red[0] * (1.0f / (float)N_B);
}

// ---------------------------------------------------------------------------
extern "C" void kernel_launch(void* const* d_in, const int* in_sizes, int n_in,
                              void* d_out, int out_size) {
    (void)in_sizes; (void)n_in; (void)out_size;
    const float* x = (const float*)d_in[0];
    const float* z = (const float*)d_in[1];
    float* out = (float*)d_out;

    cudaFuncSetAttribute(sim_kernel, cudaFuncAttributeMaxDynamicSharedMemorySize, SM_ALLOC);

    round_kernel<<<1024, 256>>>(x, z);
    sim_kernel<<<dim3(32, 64), 256, SM_ALLOC>>>();
    lse_kernel<<<64, 256>>>();
    finish_kernel<<<1, 512>>>(out);
}

// round 4
// speedup vs baseline: 2.3333x; 1.3823x over previous
#include <cuda_runtime.h>
#include <cuda_bf16.h>
#include <cstdint>
#include <math.h>

#define N_B   256
#define K_DIM 256
// mma roles: M (rows) = 128 z-rows (4 b's), N (cols) = 256 x-rows (8 a's)
#define ZR 128
#define XR 256
#define KC 64                    // bf16 per chunk = 128 B rows
#define NCHUNK (K_DIM / KC)      // 4

// smem: per chunk Z 128*128B=16KB + X 256*128B=32KB = 48KB; all 4 chunks resident
#define CHUNK_BYTES 49152
#define SM_ALLOC (NCHUNK * CHUNK_BYTES + 1024)

// device scratch (allocation-free rule)
__device__ __align__(1024) __nv_bfloat16 g_xh[(size_t)N_B * 32 * K_DIM];
__device__ __align__(1024) __nv_bfloat16 g_zh[(size_t)N_B * 32 * K_DIM];
__device__ __align__(256)  float g_S[N_B * N_B];
__device__ float g_part[2 * N_B];

// ---------------------------------------------------------------------------
__device__ __forceinline__ uint32_t smem_u32(const void* p) {
    uint32_t a;
    asm("{ .reg .u64 t; cvta.to.shared.u64 t, %1; cvt.u32.u64 %0, t; }" : "=r"(a) : "l"(p));
    return a;
}
__device__ __forceinline__ void cp16(uint32_t dst, const void* src) {
    asm volatile("cp.async.cg.shared.global [%0], [%1], 16;\n" :: "r"(dst), "l"(src));
}
__device__ __forceinline__ void ldm_x4(uint32_t r[4], uint32_t addr) {
    asm volatile("ldmatrix.sync.aligned.m8n8.x4.shared.b16 {%0,%1,%2,%3}, [%4];"
                 : "=r"(r[0]), "=r"(r[1]), "=r"(r[2]), "=r"(r[3]) : "r"(addr));
}
__device__ __forceinline__ void mma_bf16(float c[4], const uint32_t a[4], const uint32_t b0,
                                         const uint32_t b1) {
    asm volatile(
        "mma.sync.aligned.m16n8k16.row.col.f32.bf16.bf16.f32 "
        "{%0,%1,%2,%3}, {%4,%5,%6,%7}, {%8,%9}, {%0,%1,%2,%3};\n"
        : "+f"(c[0]), "+f"(c[1]), "+f"(c[2]), "+f"(c[3])
        : "r"(a[0]), "r"(a[1]), "r"(a[2]), "r"(a[3]), "r"(b0), "r"(b1));
}
__device__ __forceinline__ uint32_t swz(uint32_t off) {
    return off ^ ((off >> 3) & 0x70);
}

// ---------------------------------------------------------------------------
// Phase 0: fp32 -> bf16 (rn); exact-fit grid, 2 independent float4/thread
// ---------------------------------------------------------------------------
__global__ void round_kernel(const float* __restrict__ x, const float* __restrict__ z) {
    int i = blockIdx.x * blockDim.x + threadIdx.x;   // 0 .. 524287
    float4 vx = ((const float4*)x)[i];
    float4 vz = ((const float4*)z)[i];
    __nv_bfloat162 x0 = __floats2bfloat162_rn(vx.x, vx.y);
    __nv_bfloat162 x1 = __floats2bfloat162_rn(vx.z, vx.w);
    __nv_bfloat162 z0 = __floats2bfloat162_rn(vz.x, vz.y);
    __nv_bfloat162 z1 = __floats2bfloat162_rn(vz.z, vz.w);
    uint2 ox, oz;
    ox.x = *(uint32_t*)&x0; ox.y = *(uint32_t*)&x1;
    oz.x = *(uint32_t*)&z0; oz.y = *(uint32_t*)&z1;
    *(uint2*)(g_xh + 4 * (size_t)i) = ox;
    *(uint2*)(g_zh + 4 * (size_t)i) = oz;
}

// ---------------------------------------------------------------------------
// Phase 1: bf16 mma.sync GEMM (rows=z, cols=x) + cheap fused softmax epilogue
// ---------------------------------------------------------------------------
__device__ __forceinline__ void load_chunk(uint32_t zs, uint32_t xs,
                                           const __nv_bfloat16* __restrict__ zg,
                                           const __nv_bfloat16* __restrict__ xg,
                                           int c, int tid) {
    const int kc = c * KC;
#pragma unroll
    for (int q = 0; q < 4; ++q) {            // Z tile: 128 rows x 8 segs
        int it = tid + 256 * q;
        int row = it >> 3, s = it & 7;
        cp16(zs + swz(row * 128 + s * 16), zg + (size_t)row * K_DIM + kc + s * 8);
    }
#pragma unroll
    for (int q = 0; q < 8; ++q) {            // X tile: 256 rows x 8 segs
        int it = tid + 256 * q;
        int row = it >> 3, s = it & 7;
        cp16(xs + swz(row * 128 + s * 16), xg + (size_t)row * K_DIM + kc + s * 8);
    }
    asm volatile("cp.async.commit_group;\n" ::);
}

__device__ __forceinline__ void compute_chunk(uint32_t zs, uint32_t xs,
                                              int m0, int n0, int lane,
                                              float acc[4][8][4]) {
    const int a_row16 = lane & 15;
    const int a_half  = lane >> 4;
    const int b_grp   = lane >> 3;
    const int b_row   = lane & 7;
#pragma unroll
    for (int ks = 0; ks < 4; ++ks) {
        const uint32_t kcol = ks * 32;
        uint32_t a[4][4];
#pragma unroll
        for (int mf = 0; mf < 4; ++mf) {     // A operand = z rows
            int row = m0 + mf * 16 + a_row16;
            ldm_x4(a[mf], zs + swz((uint32_t)row * 128 + kcol + a_half * 16));
        }
        uint32_t b[4][4];
#pragma unroll
        for (int pf = 0; pf < 4; ++pf) {     // B operand = x rows
            int row = n0 + pf * 16 + (b_grp >> 1) * 8 + b_row;
            ldm_x4(b[pf], xs + swz((uint32_t)row * 128 + kcol + (b_grp & 1) * 16));
        }
#pragma unroll
        for (int mf = 0; mf < 4; ++mf)
#pragma unroll
            for (int nf = 0; nf < 8; ++nf)
                mma_bf16(acc[mf][nf], a[mf], b[nf >> 1][(nf & 1) * 2],
                         b[nf >> 1][(nf & 1) * 2 + 1]);
    }
}

__global__ void __launch_bounds__(256, 1) sim_kernel() {
    extern __shared__ char sm_raw[];
    uint32_t base = (smem_u32(sm_raw) + 1023u) & ~1023u;

    const int tid  = threadIdx.x;
    const int lane = tid & 31;
    const int wid  = tid >> 5;
    const int w_m  = wid & 1;       // 2 warps over 128 z rows
    const int w_n  = wid >> 1;      // 4 warps over 256 x rows
    const int m0   = w_m * 64;
    const int n0   = w_n * 64;

    const __nv_bfloat16* zg = g_zh + (size_t)blockIdx.y * ZR * K_DIM;
    const __nv_bfloat16* xg = g_xh + (size_t)blockIdx.x * XR * K_DIM;

    float acc[4][8][4];
#pragma unroll
    for (int mf = 0; mf < 4; ++mf)
#pragma unroll
        for (int nf = 0; nf < 8; ++nf)
#pragma unroll
            for (int q = 0; q < 4; ++q) acc[mf][nf][q] = 0.0f;

    // issue ALL chunk loads up front (192 KB resident; no buffer reuse)
#pragma unroll
    for (int c = 0; c < NCHUNK; ++c)
        load_chunk(base + c * CHUNK_BYTES, base + c * CHUNK_BYTES + 16384, zg, xg, c, tid);

#pragma unroll
    for (int c = 0; c < NCHUNK; ++c) {
        switch (c) {
            case 0: asm volatile("cp.async.wait_group 3;\n" ::); break;
            case 1: asm volatile("cp.async.wait_group 2;\n" ::); break;
            case 2: asm volatile("cp.async.wait_group 1;\n" ::); break;
            default: asm volatile("cp.async.wait_group 0;\n" ::); break;
        }
        __syncthreads();
        compute_chunk(base + c * CHUNK_BYTES, base + c * CHUNK_BYTES + 16384,
                      m0, n0, lane, acc);
    }

    // ---- epilogue ----
    // acc row  = z row: j = m0 + mf*16 + 8*half + g   (b-group bg = mf>>1)
    // acc col  = x row: n0 + nf*8 + 2*tg + par        (a-block ab = nf>>2)
    // softmax over i (32 cols of an a-block): in-thread over 8 + shfl xor 1,2
    // then sum over j: in-thread over (mf,half) + shfl xor 4,8,16
    float sacc[2][2] = {{0.f, 0.f}, {0.f, 0.f}};   // [ab][bg]
#pragma unroll
    for (int mf = 0; mf < 4; ++mf) {
        const int bg = mf >> 1;
#pragma unroll
        for (int half = 0; half < 2; ++half) {
#pragma unroll
            for (int ab = 0; ab < 2; ++ab) {
                float v[8];
#pragma unroll
                for (int f = 0; f < 4; ++f) {
                    v[f * 2 + 0] = acc[mf][ab * 4 + f][half * 2 + 0];
                    v[f * 2 + 1] = acc[mf][ab * 4 + f][half * 2 + 1];
                }
                float mx = v[0];
#pragma unroll
                for (int t = 1; t < 8; ++t) mx = fmaxf(mx, v[t]);
                mx = fmaxf(mx, __shfl_xor_sync(0xffffffffu, mx, 1));
                mx = fmaxf(mx, __shfl_xor_sync(0xffffffffu, mx, 2));
                float den = 0.f, num = 0.f;
#pragma unroll
                for (int t = 0; t < 8; ++t) {
                    float e = __expf(v[t] - mx);
                    den += e;
                    num += e * v[t];
                }
                den += __shfl_xor_sync(0xffffffffu, den, 1);
                num += __shfl_xor_sync(0xffffffffu, num, 1);
                den += __shfl_xor_sync(0xffffffffu, den, 2);
                num += __shfl_xor_sync(0xffffffffu, num, 2);
                sacc[ab][bg] += num / den;     // per-j contribution
            }
        }
    }
#pragma unroll
    for (int ab = 0; ab < 2; ++ab)
#pragma unroll
        for (int bg = 0; bg < 2; ++bg) {
            float s = sacc[ab][bg];
            s += __shfl_xor_sync(0xffffffffu, s, 4);
            s += __shfl_xor_sync(0xffffffffu, s, 8);
            s += __shfl_xor_sync(0xffffffffu, s, 16);
            if (lane == 0) {
                int aIdx = blockIdx.x * 8 + w_n * 2 + ab;
                int bIdx = blockIdx.y * 4 + w_m * 2 + bg;
                g_S[aIdx * N_B + bIdx] = s * (1.0f / 32.0f);
            }
        }
}

// ---------------------------------------------------------------------------
// Phase 2a: per-n row/col logsumexp minus diag (512 warps)
// ---------------------------------------------------------------------------
__global__ void lse_kernel() {
    const int wg   = blockIdx.x * (blockDim.x >> 5) + (threadIdx.x >> 5);
    const int lane = threadIdx.x & 31;
    const int n    = wg & (N_B - 1);
    const bool col = wg >= N_B;

    float v[8];
#pragma unroll
    for (int k = 0; k < 8; ++k) {
        int idx = lane + 32 * k;
        v[k] = col ? g_S[idx * N_B + n] : g_S[n * N_B + idx];
    }
    float m = v[0];
#pragma unroll
    for (int k = 1; k < 8; ++k) m = fmaxf(m, v[k]);
#pragma unroll
    for (int o = 16; o > 0; o >>= 1) m = fmaxf(m, __shfl_xor_sync(0xffffffffu, m, o));
    float s = 0.f;
#pragma unroll
    for (int k = 0; k < 8; ++k) s += __expf(v[k] - m);
#pragma unroll
    for (int o = 16; o > 0; o >>= 1) s += __shfl_xor_sync(0xffffffffu, s, o);
    if (lane == 0) g_part[wg] = m + logf(s) - g_S[n * N_B + n];
}

__global__ void finish_kernel(float* __restrict__ out) {
    __shared__ float red[512];
    int t = threadIdx.x;
    red[t] = g_part[t];
    __syncthreads();
#pragma unroll
    for (int o = 256; o > 0; o >>= 1) {
        if (t < o) red[t] += red[t + o];
        __syncthreads();
    }
    if (t == 0) out[0] = red[0] * (1.0f / (float)N_B);
}

// ---------------------------------------------------------------------------
extern "C" void kernel_launch(void* const* d_in, const int* in_sizes, int n_in,
                              void* d_out, int out_size) {
    (void)in_sizes; (void)n_in; (void)out_size;
    const float* x = (const float*)d_in[0];
    const float* z = (const float*)d_in[1];
    float* out = (float*)d_out;

    cudaFuncSetAttribute(sim_kernel, cudaFuncAttributeMaxDynamicSharedMemorySize, SM_ALLOC);

    round_kernel<<<2048, 256>>>(x, z);
    sim_kernel<<<dim3(32, 64), 256, SM_ALLOC>>>();
    lse_kernel<<<64, 256>>>();
    finish_kernel<<<1, 512>>>(out);
}

// round 5
// speedup vs baseline: 2.7189x; 1.1653x over previous
#include <cuda_runtime.h>
#include <cuda_bf16.h>
#include <cstdint>
#include <math.h>

#define N_B   256
#define K_DIM 256
// mma roles: M = 128 z-rows (4 b's), N = 128 x-rows (4 a's) per CTA
#define KC 64                    // bf16 per chunk = 128 B rows
#define NCHUNK (K_DIM / KC)      // 4

// per stage: Z 128*128B = 16KB + X 128*128B = 16KB = 32KB; 3 stages = 96KB
#define STAGE_BYTES 32768
#define SM_ALLOC (3 * STAGE_BYTES + 1024)

// device scratch (allocation-free rule)
__device__ __align__(1024) __nv_bfloat16 g_xh[(size_t)N_B * 32 * K_DIM];
__device__ __align__(1024) __nv_bfloat16 g_zh[(size_t)N_B * 32 * K_DIM];
__device__ __align__(256)  float g_S[N_B * N_B];
__device__ __align__(256)  float g_St[N_B * N_B];

// ---------------------------------------------------------------------------
__device__ __forceinline__ uint32_t smem_u32(const void* p) {
    uint32_t a;
    asm("{ .reg .u64 t; cvta.to.shared.u64 t, %1; cvt.u32.u64 %0, t; }" : "=r"(a) : "l"(p));
    return a;
}
__device__ __forceinline__ void cp16(uint32_t dst, const void* src) {
    asm volatile("cp.async.cg.shared.global [%0], [%1], 16;\n" :: "r"(dst), "l"(src));
}
__device__ __forceinline__ void ldm_x4(uint32_t r[4], uint32_t addr) {
    asm volatile("ldmatrix.sync.aligned.m8n8.x4.shared.b16 {%0,%1,%2,%3}, [%4];"
                 : "=r"(r[0]), "=r"(r[1]), "=r"(r[2]), "=r"(r[3]) : "r"(addr));
}
__device__ __forceinline__ void mma_bf16(float c[4], const uint32_t a[4], const uint32_t b0,
                                         const uint32_t b1) {
    asm volatile(
        "mma.sync.aligned.m16n8k16.row.col.f32.bf16.bf16.f32 "
        "{%0,%1,%2,%3}, {%4,%5,%6,%7}, {%8,%9}, {%0,%1,%2,%3};\n"
        : "+f"(c[0]), "+f"(c[1]), "+f"(c[2]), "+f"(c[3])
        : "r"(a[0]), "r"(a[1]), "r"(a[2]), "r"(a[3]), "r"(b0), "r"(b1));
}
__device__ __forceinline__ uint32_t swz(uint32_t off) {
    return off ^ ((off >> 3) & 0x70);
}

// ---------------------------------------------------------------------------
// Phase 0: fp32 -> bf16 (rn)
// ---------------------------------------------------------------------------
__global__ void round_kernel(const float* __restrict__ x, const float* __restrict__ z) {
    int i = blockIdx.x * blockDim.x + threadIdx.x;   // 0 .. 524287
    float4 vx = ((const float4*)x)[i];
    float4 vz = ((const float4*)z)[i];
    __nv_bfloat162 x0 = __floats2bfloat162_rn(vx.x, vx.y);
    __nv_bfloat162 x1 = __floats2bfloat162_rn(vx.z, vx.w);
    __nv_bfloat162 z0 = __floats2bfloat162_rn(vz.x, vz.y);
    __nv_bfloat162 z1 = __floats2bfloat162_rn(vz.z, vz.w);
    uint2 ox, oz;
    ox.x = *(uint32_t*)&x0; ox.y = *(uint32_t*)&x1;
    oz.x = *(uint32_t*)&z0; oz.y = *(uint32_t*)&z1;
    *(uint2*)(g_xh + 4 * (size_t)i) = ox;
    *(uint2*)(g_zh + 4 * (size_t)i) = oz;
}

// ---------------------------------------------------------------------------
// Phase 1: bf16 mma.sync (rows = z, cols = x), 128x128 tile, 2 CTAs/SM
// ---------------------------------------------------------------------------
__device__ __forceinline__ void load_chunk(uint32_t stg,
                                           const __nv_bfloat16* __restrict__ zg,
                                           const __nv_bfloat16* __restrict__ xg,
                                           int c, int tid) {
    const int kc = c * KC;
    const uint32_t zs = stg;
    const uint32_t xs = stg + 16384;
#pragma unroll
    for (int q = 0; q < 4; ++q) {            // Z: 128 rows x 8 segs
        int it = tid + 256 * q;
        int row = it >> 3, s = it & 7;
        cp16(zs + swz(row * 128 + s * 16), zg + (size_t)row * K_DIM + kc + s * 8);
    }
#pragma unroll
    for (int q = 0; q < 4; ++q) {            // X: 128 rows x 8 segs
        int it = tid + 256 * q;
        int row = it >> 3, s = it & 7;
        cp16(xs + swz(row * 128 + s * 16), xg + (size_t)row * K_DIM + kc + s * 8);
    }
    asm volatile("cp.async.commit_group;\n" ::);
}

__device__ __forceinline__ void compute_chunk(uint32_t stg, int m0, int n0, int lane,
                                              float acc[4][4][4]) {
    const uint32_t zs = stg;
    const uint32_t xs = stg + 16384;
    const int a_row16 = lane & 15;
    const int a_half  = lane >> 4;
    const int b_grp   = lane >> 3;
    const int b_row   = lane & 7;
#pragma unroll
    for (int ks = 0; ks < 4; ++ks) {
        const uint32_t kcol = ks * 32;
        uint32_t a[4][4];
#pragma unroll
        for (int mf = 0; mf < 4; ++mf) {     // A = z rows
            int row = m0 + mf * 16 + a_row16;
            ldm_x4(a[mf], zs + swz((uint32_t)row * 128 + kcol + a_half * 16));
        }
        uint32_t b[2][4];
#pragma unroll
        for (int pf = 0; pf < 2; ++pf) {     // B = x rows (n range 32)
            int row = n0 + pf * 16 + (b_grp >> 1) * 8 + b_row;
            ldm_x4(b[pf], xs + swz((uint32_t)row * 128 + kcol + (b_grp & 1) * 16));
        }
#pragma unroll
        for (int mf = 0; mf < 4; ++mf)
#pragma unroll
            for (int nf = 0; nf < 4; ++nf)
                mma_bf16(acc[mf][nf], a[mf], b[nf >> 1][(nf & 1) * 2],
                         b[nf >> 1][(nf & 1) * 2 + 1]);
    }
}

__global__ void __launch_bounds__(256, 2) sim_kernel() {
    extern __shared__ char sm_raw[];
    uint32_t base = (smem_u32(sm_raw) + 1023u) & ~1023u;

    const int tid  = threadIdx.x;
    const int lane = tid & 31;
    const int wid  = tid >> 5;
    const int w_m  = wid & 1;       // 2 warps over 128 z rows
    const int w_n  = wid >> 1;      // 4 warps over 128 x rows
    const int m0   = w_m * 64;
    const int n0   = w_n * 32;

    const __nv_bfloat16* zg = g_zh + (size_t)blockIdx.y * 128 * K_DIM;
    const __nv_bfloat16* xg = g_xh + (size_t)blockIdx.x * 128 * K_DIM;

    const uint32_t st0 = base, st1 = base + STAGE_BYTES, st2 = base + 2 * STAGE_BYTES;

    float acc[4][4][4];
#pragma unroll
    for (int mf = 0; mf < 4; ++mf)
#pragma unroll
        for (int nf = 0; nf < 4; ++nf)
#pragma unroll
            for (int q = 0; q < 4; ++q) acc[mf][nf][q] = 0.0f;

    load_chunk(st0, zg, xg, 0, tid);
    load_chunk(st1, zg, xg, 1, tid);
    load_chunk(st2, zg, xg, 2, tid);

    asm volatile("cp.async.wait_group 2;\n" ::);
    __syncthreads();
    compute_chunk(st0, m0, n0, lane, acc);
    __syncthreads();                          // WAR before refilling stage 0
    load_chunk(st0, zg, xg, 3, tid);

    asm volatile("cp.async.wait_group 2;\n" ::);
    __syncthreads();
    compute_chunk(st1, m0, n0, lane, acc);

    asm volatile("cp.async.wait_group 1;\n" ::);
    __syncthreads();
    compute_chunk(st2, m0, n0, lane, acc);

    asm volatile("cp.async.wait_group 0;\n" ::);
    __syncthreads();
    compute_chunk(st0, m0, n0, lane, acc);

    // ---- epilogue: softmax over i (this warp's single a-block), sum over j ----
    // acc row = z row j = m0 + mf*16 + 8*half + (lane>>2); b_local = w_m*2 + (mf>>1)
    // acc col = x row   = n0 + nf*8 + 2*(lane&3) + par;    a_local = w_n
    float sacc[2] = {0.f, 0.f};               // [bg = mf>>1]
#pragma unroll
    for (int mf = 0; mf < 4; ++mf) {
        const int bg = mf >> 1;
#pragma unroll
        for (int half = 0; half < 2; ++half) {
            float v[8];
#pragma unroll
            for (int nf = 0; nf < 4; ++nf) {
                v[nf * 2 + 0] = acc[mf][nf][half * 2 + 0];
                v[nf * 2 + 1] = acc[mf][nf][half * 2 + 1];
            }
            float mx = v[0];
#pragma unroll
            for (int t = 1; t < 8; ++t) mx = fmaxf(mx, v[t]);
            mx = fmaxf(mx, __shfl_xor_sync(0xffffffffu, mx, 1));
            mx = fmaxf(mx, __shfl_xor_sync(0xffffffffu, mx, 2));
            float den = 0.f, num = 0.f;
#pragma unroll
            for (int t = 0; t < 8; ++t) {
                float e = __expf(v[t] - mx);
                den += e;
                num += e * v[t];
            }
            den += __shfl_xor_sync(0xffffffffu, den, 1);
            num += __shfl_xor_sync(0xffffffffu, num, 1);
            den += __shfl_xor_sync(0xffffffffu, den, 2);
            num += __shfl_xor_sync(0xffffffffu, num, 2);
            sacc[bg] += num / den;
        }
    }
#pragma unroll
    for (int bg = 0; bg < 2; ++bg) {
        float s = sacc[bg];
        s += __shfl_xor_sync(0xffffffffu, s, 4);
        s += __shfl_xor_sync(0xffffffffu, s, 8);
        s += __shfl_xor_sync(0xffffffffu, s, 16);
        if (lane == 0) {
            int aIdx = blockIdx.x * 4 + w_n;
            int bIdx = blockIdx.y * 4 + w_m * 2 + bg;
            float val = s * (1.0f / 32.0f);
            g_S[aIdx * N_B + bIdx]  = val;
            g_St[bIdx * N_B + aIdx] = val;
        }
    }
}

// ---------------------------------------------------------------------------
// Phase 2: fused loss. 1 block, 1024 threads = 32 warps; 512 lse tasks.
// Row tasks read g_S rows; col tasks read g_St rows (both coalesced).
// ---------------------------------------------------------------------------
__global__ void loss_kernel(float* __restrict__ out) {
    __shared__ float part[512];
    __shared__ float red[256];
    const int warp = threadIdx.x >> 5;
    const int lane = threadIdx.x & 31;

#pragma unroll 1
    for (int t = 0; t < 16; ++t) {
        const int id = warp + t * 32;          // 0..511
        const int n  = id & (N_B - 1);
        const float* row = (id < N_B) ? (g_S + n * N_B) : (g_St + n * N_B);
        float4 r0 = ((const float4*)row)[lane];
        float4 r1 = ((const float4*)row)[lane + 32];
        float m = fmaxf(fmaxf(fmaxf(r0.x, r0.y), fmaxf(r0.z, r0.w)),
                        fmaxf(fmaxf(r1.x, r1.y), fmaxf(r1.z, r1.w)));
#pragma unroll
        for (int o = 16; o > 0; o >>= 1) m = fmaxf(m, __shfl_xor_sync(0xffffffffu, m, o));
        float s = __expf(r0.x - m) + __expf(r0.y - m) + __expf(r0.z - m) + __expf(r0.w - m)
                + __expf(r1.x - m) + __expf(r1.y - m) + __expf(r1.z - m) + __expf(r1.w - m);
#pragma unroll
        for (int o = 16; o > 0; o >>= 1) s += __shfl_xor_sync(0xffffffffu, s, o);
        if (lane == 0) part[id] = m + logf(s) - g_S[n * N_B + n];
    }
    __syncthreads();

    const int tid = threadIdx.x;
    if (tid < 256) red[tid] = part[tid] + part[tid + 256];
    __syncthreads();
#pragma unroll
    for (int o = 128; o > 0; o >>= 1) {
        if (tid < o) red[tid] += red[tid + o];
        __syncthreads();
    }
    if (tid == 0) out[0] = red[0] * (1.0f / (float)N_B);
}

// ---------------------------------------------------------------------------
extern "C" void kernel_launch(void* const* d_in, const int* in_sizes, int n_in,
                              void* d_out, int out_size) {
    (void)in_sizes; (void)n_in; (void)out_size;
    const float* x = (const float*)d_in[0];
    const float* z = (const float*)d_in[1];
    float* out = (float*)d_out;

    cudaFuncSetAttribute(sim_kernel, cudaFuncAttributeMaxDynamicSharedMemorySize, SM_ALLOC);

    round_kernel<<<2048, 256>>>(x, z);
    sim_kernel<<<dim3(64, 64), 256, SM_ALLOC>>>();
    loss_kernel<<<1, 1024>>>(out);
}